// round 1
// baseline (speedup 1.0000x reference)
#include <cuda_runtime.h>

#define N_NODES 100000
#define F_IN    512
#define HIDDEN  64

#define TM 128          // rows per block tile
#define KC 64           // k-chunk
#define WX 128          // Xs row width (floats), transposed layout [k][m]
#define WW 64           // Ws row width (floats), layout [k][n]
#define NTHREADS 256

// 25.6MB scratch for logits (static __device__ — allowed, no runtime alloc)
__device__ float g_logits[(long long)N_NODES * HIDDEN];

// ---- packed f32x2 helpers (sm_100+ PTX) ----
#define PACK2F(d, x)    asm("mov.b64 %0, {%1, %1};" : "=l"(d) : "r"(__float_as_uint(x)))
#define PACK2(d, a, b)  asm("mov.b64 %0, {%1, %2};" : "=l"(d) : "r"(__float_as_uint(a)), "r"(__float_as_uint(b)))
#define UNPACK2(lo, hi, s) asm("mov.b64 {%0, %1}, %2;" : "=r"(lo), "=r"(hi) : "l"(s))
#define FMA2(acc, a, b) asm("fma.rn.f32x2 %0, %1, %2, %0;" : "+l"(acc) : "l"(a), "l"(b))

// One k-step of the register tile: 4 row-pairs x 4 cols, 16 f32x2 FMAs
#define GEMM_TILE_STEP(ACC, XR, WR) do {                                       \
    ulonglong2 _xa = *(const ulonglong2*)(XR);                                 \
    ulonglong2 _xb = *(const ulonglong2*)((XR) + 4);                           \
    float4 _wv = *(const float4*)(WR);                                         \
    unsigned long long _w0, _w1, _w2, _w3;                                     \
    PACK2F(_w0, _wv.x); PACK2F(_w1, _wv.y); PACK2F(_w2, _wv.z); PACK2F(_w3, _wv.w); \
    FMA2(ACC[0][0], _xa.x, _w0); FMA2(ACC[0][1], _xa.x, _w1);                  \
    FMA2(ACC[0][2], _xa.x, _w2); FMA2(ACC[0][3], _xa.x, _w3);                  \
    FMA2(ACC[1][0], _xa.y, _w0); FMA2(ACC[1][1], _xa.y, _w1);                  \
    FMA2(ACC[1][2], _xa.y, _w2); FMA2(ACC[1][3], _xa.y, _w3);                  \
    FMA2(ACC[2][0], _xb.x, _w0); FMA2(ACC[2][1], _xb.x, _w1);                  \
    FMA2(ACC[2][2], _xb.x, _w2); FMA2(ACC[2][3], _xb.x, _w3);                  \
    FMA2(ACC[3][0], _xb.y, _w0); FMA2(ACC[3][1], _xb.y, _w1);                  \
    FMA2(ACC[3][2], _xb.y, _w2); FMA2(ACC[3][3], _xb.y, _w3);                  \
  } while (0)

// Fused: logits = relu(X@W1 + b1) @ W2 + b2   -> g_logits
__global__ __launch_bounds__(NTHREADS, 2) void mlp_kernel(
    const float* __restrict__ X,
    const float* __restrict__ W1, const float* __restrict__ b1,
    const float* __restrict__ W2, const float* __restrict__ b2)
{
  __shared__ float Xs[KC * WX];   // transposed X chunk [k][m]; later reused as hs[c][m]
  __shared__ float Ws[KC * WW];   // W1 chunk [k][n];       later reused as W2 [c][n]

  const int tid  = threadIdx.x;
  const int cg   = tid & 15;      // 16 col groups  x 4 cols
  const int rg   = tid >> 4;      // 16 row groups  x 8 rows
  const int row0 = blockIdx.x * TM;

  unsigned long long acc[4][4];   // [row-pair][col], f32x2 packed
#pragma unroll
  for (int p = 0; p < 4; ++p)
#pragma unroll
    for (int j = 0; j < 4; ++j) acc[p][j] = 0ULL;

  for (int ch = 0; ch < F_IN / KC; ++ch) {
    const int kc = ch * KC;
    // ---- stage X tile transposed: Xs[k][m] ----
#pragma unroll
    for (int it = 0; it < (TM * KC / 4) / NTHREADS; ++it) {   // 8 iters
      int idx = it * NTHREADS + tid;
      int a   = idx & 3;                // k4 low bits
      int m   = (idx >> 2) & 127;       // row within tile
      int khi = idx >> 9;               // k4 high bits
      int k4  = khi * 4 + a;            // float4 group along k (0..15)
      int gm  = row0 + m;
      float4 v = make_float4(0.f, 0.f, 0.f, 0.f);
      if (gm < N_NODES)
        v = *(const float4*)(X + (long long)gm * F_IN + kc + k4 * 4);
      Xs[(k4 * 4 + 0) * WX + m] = v.x;
      Xs[(k4 * 4 + 1) * WX + m] = v.y;
      Xs[(k4 * 4 + 2) * WX + m] = v.z;
      Xs[(k4 * 4 + 3) * WX + m] = v.w;
    }
    // ---- stage W1 chunk: Ws[k][n] ----
#pragma unroll
    for (int it = 0; it < (KC * HIDDEN / 4) / NTHREADS; ++it) {  // 4 iters
      int idx = it * NTHREADS + tid;
      int k  = idx >> 4;
      int n4 = (idx & 15) * 4;
      *(float4*)(Ws + k * WW + n4) =
          *(const float4*)(W1 + (long long)(kc + k) * HIDDEN + n4);
    }
    __syncthreads();
#pragma unroll 8
    for (int kk = 0; kk < KC; ++kk) {
      const float* xr = Xs + kk * WX + rg * 8;
      const float* wr = Ws + kk * WW + cg * 4;
      GEMM_TILE_STEP(acc, xr, wr);
    }
    __syncthreads();
  }

  // ---- epilogue 1: h = relu(acc + b1); store transposed hs[c][m] into Xs; load W2 into Ws ----
  {
    float4 b1v = *(const float4*)(b1 + cg * 4);
    float bb[4] = {b1v.x, b1v.y, b1v.z, b1v.w};
#pragma unroll
    for (int p = 0; p < 4; ++p)
#pragma unroll
      for (int j = 0; j < 4; ++j) {
        unsigned lo, hi;
        UNPACK2(lo, hi, acc[p][j]);
        float flo = fmaxf(__uint_as_float(lo) + bb[j], 0.f);
        float fhi = fmaxf(__uint_as_float(hi) + bb[j], 0.f);
        unsigned long long pr;
        PACK2(pr, flo, fhi);
        *(unsigned long long*)(Xs + (cg * 4 + j) * WX + rg * 8 + 2 * p) = pr;
      }
#pragma unroll
    for (int it = 0; it < (HIDDEN * HIDDEN / 4) / NTHREADS; ++it) {  // 4 iters
      int idx = it * NTHREADS + tid;
      int k  = idx >> 4;
      int n4 = (idx & 15) * 4;
      *(float4*)(Ws + k * WW + n4) = *(const float4*)(W2 + k * HIDDEN + n4);
    }
  }
  __syncthreads();

  // ---- GEMM2: logits = h @ W2 ----
  unsigned long long acc2[4][4];
#pragma unroll
  for (int p = 0; p < 4; ++p)
#pragma unroll
    for (int j = 0; j < 4; ++j) acc2[p][j] = 0ULL;
#pragma unroll 8
  for (int kk = 0; kk < HIDDEN; ++kk) {
    const float* xr = Xs + kk * WX + rg * 8;
    const float* wr = Ws + kk * WW + cg * 4;
    GEMM_TILE_STEP(acc2, xr, wr);
  }

  // ---- epilogue 2: + b2, store row-major to g_logits ----
  float4 b2v = *(const float4*)(b2 + cg * 4);
#pragma unroll
  for (int p = 0; p < 4; ++p) {
    unsigned lo0, hi0, lo1, hi1, lo2, hi2, lo3, hi3;
    UNPACK2(lo0, hi0, acc2[p][0]);
    UNPACK2(lo1, hi1, acc2[p][1]);
    UNPACK2(lo2, hi2, acc2[p][2]);
    UNPACK2(lo3, hi3, acc2[p][3]);
    int gm0 = row0 + rg * 8 + 2 * p;
    if (gm0 < N_NODES) {
      float4 r;
      r.x = __uint_as_float(lo0) + b2v.x;
      r.y = __uint_as_float(lo1) + b2v.y;
      r.z = __uint_as_float(lo2) + b2v.z;
      r.w = __uint_as_float(lo3) + b2v.w;
      *(float4*)(g_logits + (long long)gm0 * HIDDEN + cg * 4) = r;
    }
    int gm1 = gm0 + 1;
    if (gm1 < N_NODES) {
      float4 r;
      r.x = __uint_as_float(hi0) + b2v.x;
      r.y = __uint_as_float(hi1) + b2v.y;
      r.z = __uint_as_float(hi2) + b2v.z;
      r.w = __uint_as_float(hi3) + b2v.w;
      *(float4*)(g_logits + (long long)gm1 * HIDDEN + cg * 4) = r;
    }
  }
}

__global__ void zero_kernel(float4* __restrict__ out, int n4)
{
  int stride = gridDim.x * blockDim.x;
  for (int i = blockIdx.x * blockDim.x + threadIdx.x; i < n4; i += stride)
    out[i] = make_float4(0.f, 0.f, 0.f, 0.f);
}

// out[row] += val * logits[col]   (two edges per warp; 16 lanes x float4 per edge)
__global__ __launch_bounds__(256) void scatter_kernel(
    const int* __restrict__ rows, const int* __restrict__ cols,
    const float* __restrict__ vals, float* __restrict__ out, int E)
{
  const int lane = threadIdx.x & 31;
  const int l16  = lane & 15;
  const int half = lane >> 4;
  const int warp = (blockIdx.x * blockDim.x + threadIdx.x) >> 5;
  const int nw   = (gridDim.x * blockDim.x) >> 5;

  for (int base = warp * 2; base < E; base += nw * 2) {
    int e = base + half;
    if (e < E) {
      int   r = __ldg(rows + e);
      int   c = __ldg(cols + e);
      float v = __ldg(vals + e);
      float4 p = *(const float4*)(g_logits + (long long)c * HIDDEN + l16 * 4);
      float4 q = make_float4(p.x * v, p.y * v, p.z * v, p.w * v);
      float* dst = out + (long long)r * HIDDEN + l16 * 4;
      asm volatile("red.global.add.v4.f32 [%0], {%1, %2, %3, %4};"
                   :: "l"(dst), "f"(q.x), "f"(q.y), "f"(q.z), "f"(q.w)
                   : "memory");
    }
  }
}

extern "C" void kernel_launch(void* const* d_in, const int* in_sizes, int n_in,
                              void* d_out, int out_size)
{
  const float* X     = (const float*)d_in[0];
  const int*   erows = (const int*)  d_in[1];
  const int*   ecols = (const int*)  d_in[2];
  const float* evals = (const float*)d_in[3];
  const float* W1    = (const float*)d_in[4];
  const float* b1    = (const float*)d_in[5];
  const float* W2    = (const float*)d_in[6];
  const float* b2    = (const float*)d_in[7];
  float* out = (float*)d_out;
  const int E = in_sizes[1];

  // zero output first (out is poisoned before timing)
  zero_kernel<<<2048, 256>>>((float4*)out, out_size / 4);

  // fused MLP -> g_logits
  const int grid = (N_NODES + TM - 1) / TM;   // 782
  mlp_kernel<<<grid, NTHREADS>>>(X, W1, b1, W2, b2);

  // COO scatter with vectorized L2 reductions
  scatter_kernel<<<2048, 256>>>(erows, ecols, evals, out, E);
}